// round 3
// baseline (speedup 1.0000x reference)
#include <cuda_runtime.h>
#include <cuda_bf16.h>
#include <cstdint>
#include <cstddef>

// ============================================================================
// SparseBlockSeries: 4 x [subm_conv -> BN -> leaky -> subm_conv -> BN -> +res -> leaky]
// N=131072 rows, C=64 channels, K=9 neighbors, fp32.
// ============================================================================

#define CC   64
#define KK   9
#define TM   128
#define NMAX 131072
#define NCTA (NMAX / TM)
#define LEAK 0.33f

// Dynamic smem layout: W (9*64*64 f) | A double buffer (2*128*64 f) | idx (128*9 i) | ss (128*9 i)
#define SMEM_BYTES ((KK*CC*CC + 2*TM*CC) * 4 + (TM*KK) * 4 * 2)

__device__ float g_T[(size_t)NMAX * CC];
__device__ float g_Y[(size_t)NMAX * CC];
__device__ float g_X[(size_t)NMAX * CC];
__device__ float g_part[(size_t)NCTA * 128];
__device__ float g_scale[CC];
__device__ float g_shift[CC];
__device__ int   g_mask_mode;   // 0 = uint8, 1 = int32, 2 = float32

// ---- f32x2 packed math helpers (sm_103a) -----------------------------------
#define FMA2(d, a, b) \
    asm("fma.rn.f32x2 %0, %1, %2, %0;" : "+l"(d) : "l"(a), "l"(b))

__device__ __forceinline__ unsigned long long pack2(float v) {
    unsigned long long d;
    unsigned u = __float_as_uint(v);
    asm("mov.b64 %0, {%1, %1};" : "=l"(d) : "r"(u));
    return d;
}
__device__ __forceinline__ void unpack2(unsigned long long v, float& lo, float& hi) {
    unsigned a, b;
    asm("mov.b64 {%0, %1}, %2;" : "=r"(a), "=r"(b) : "l"(v));
    lo = __uint_as_float(a);
    hi = __uint_as_float(b);
}
__device__ __forceinline__ void cpa16(unsigned dst, const void* src, int src_size) {
    asm volatile("cp.async.cg.shared.global [%0], [%1], 16, %2;"
                 :: "r"(dst), "l"(src), "r"(src_size) : "memory");
}

// ---- mask dtype detection ---------------------------------------------------
__global__ void detect_kernel(const unsigned* __restrict__ m) {
    if (threadIdx.x == 0 && blockIdx.x == 0) {
        int f32ok = 1;
        unsigned upper = 0;
        for (int i = 0; i < 256; i++) {
            unsigned w = m[i];
            if (w != 0u && w != 0x3F800000u) f32ok = 0;
            upper |= (w & 0xFFFFFF00u);
        }
        g_mask_mode = f32ok ? 2 : (upper ? 0 : 1);
    }
}

// ---- fused gather-GEMM conv + BN partial stats ------------------------------
__global__ void __launch_bounds__(256) conv_kernel(
    const float* __restrict__ in, const float* __restrict__ w,
    const int* __restrict__ nidx, const void* __restrict__ nmask,
    float* __restrict__ out, float* __restrict__ partials)
{
    extern __shared__ float smem[];
    float* Wp    = smem;                      // permuted weights
    float* A     = smem + KK * CC * CC;       // double-buffered gathered rows
    int*   idx_s = (int*)(A + 2 * TM * CC);
    int*   ss_s  = idx_s + TM * KK;

    const int tid   = threadIdx.x;
    const int tile0 = blockIdx.x * TM;

    // preload neighbor idx + mask (as cp.async src-size 16 or 0)
    if (tid < TM) {
        const int mode = g_mask_mode;
        const long base = (long)(tile0 + tid) * KK;
        #pragma unroll
        for (int k = 0; k < KK; k++) {
            idx_s[tid * KK + k] = nidx[base + k];
            int mv;
            if (mode == 0)      mv = ((const unsigned char*)nmask)[base + k];
            else if (mode == 1) mv = ((const int*)nmask)[base + k] != 0;
            else                mv = ((const float*)nmask)[base + k] != 0.0f;
            ss_s[tid * KK + k] = mv ? 16 : 0;
        }
    }
    // preload W, chunk-permuted: 16B chunk q=d>>2 stored so thread cg's two
    // chunks (q=2cg, 2cg+1) land at positions cg and 8+cg -> both LDS.128
    // sweeps tile banks 0..31 exactly (conflict-free).
    for (int lin = tid; lin < KK * CC * (CC / 4); lin += 256) {
        const int kc = lin >> 4;       // k*64 + c
        const int d  = (lin & 15) << 2;
        const int off = ((d >> 2) & 1) * 32 + (d >> 3) * 4;
        float4 v = *(const float4*)(w + (size_t)kc * CC + d);
        *(float4*)(Wp + (size_t)kc * CC + off) = v;
    }
    __syncthreads();

    const int cg  = tid & 7;    // outputs cg*8 .. cg*8+7
    const int rg  = tid >> 3;   // rows rg*4 .. rg*4+3
    const int swz = (rg & 3) << 3;

    const int sr = tid >> 1, sh = tid & 1;   // staging: 2 threads per row
    const unsigned A_u = (unsigned)__cvta_generic_to_shared(A);
    const int s2 = ((sr >> 2) & 3) << 3;

    unsigned long long acc[4][4];
    #pragma unroll
    for (int i = 0; i < 4; i++)
        #pragma unroll
        for (int j = 0; j < 4; j++) acc[i][j] = 0ull;

    // prologue stage slice 0 into buf 0
    {
        const int id = idx_s[sr * KK + 0];
        const int ss = ss_s[sr * KK + 0];
        const float* src = in + (size_t)id * CC + sh * 32;
        const unsigned dbase = A_u + (unsigned)((sr * CC) * 4);
        #pragma unroll
        for (int j = 0; j < 8; j++) {
            const int c = sh * 32 + j * 4;
            cpa16(dbase + (unsigned)(((c ^ s2) << 2)), src + j * 4, ss);
        }
        asm volatile("cp.async.commit_group;" ::: "memory");
    }

    for (int k = 0; k < KK; k++) {
        const int buf = k & 1;
        if (k + 1 < KK) {
            const int id = idx_s[sr * KK + (k + 1)];
            const int ss = ss_s[sr * KK + (k + 1)];
            const float* src = in + (size_t)id * CC + sh * 32;
            const unsigned dbase = A_u + (unsigned)((((buf ^ 1) * TM + sr) * CC) * 4);
            #pragma unroll
            for (int j = 0; j < 8; j++) {
                const int c = sh * 32 + j * 4;
                cpa16(dbase + (unsigned)(((c ^ s2) << 2)), src + j * 4, ss);
            }
            asm volatile("cp.async.commit_group;" ::: "memory");
            asm volatile("cp.async.wait_group 1;" ::: "memory");
        } else {
            asm volatile("cp.async.wait_group 0;" ::: "memory");
        }
        __syncthreads();

        const float* Ab  = A + buf * TM * CC;
        const float* a0p = Ab + (rg * 4 + 0) * CC;
        const float* a1p = Ab + (rg * 4 + 1) * CC;
        const float* a2p = Ab + (rg * 4 + 2) * CC;
        const float* a3p = Ab + (rg * 4 + 3) * CC;
        const float* wk  = Wp + k * CC * CC + cg * 4;

        #pragma unroll
        for (int c4 = 0; c4 < CC; c4 += 4) {
            const int cb = c4 ^ swz;
            const float4 A0 = *(const float4*)(a0p + cb);
            const float4 A1 = *(const float4*)(a1p + cb);
            const float4 A2 = *(const float4*)(a2p + cb);
            const float4 A3 = *(const float4*)(a3p + cb);
            const float* f0 = (const float*)&A0;
            const float* f1 = (const float*)&A1;
            const float* f2 = (const float*)&A2;
            const float* f3 = (const float*)&A3;
            #pragma unroll
            for (int u = 0; u < 4; u++) {
                const int c = c4 + u;
                const ulonglong2 bl = *(const ulonglong2*)(wk + c * CC);
                const ulonglong2 bh = *(const ulonglong2*)(wk + c * CC + 32);
                const unsigned long long p0 = pack2(f0[u]);
                const unsigned long long p1 = pack2(f1[u]);
                const unsigned long long p2 = pack2(f2[u]);
                const unsigned long long p3 = pack2(f3[u]);
                FMA2(acc[0][0], p0, bl.x); FMA2(acc[0][1], p0, bl.y);
                FMA2(acc[0][2], p0, bh.x); FMA2(acc[0][3], p0, bh.y);
                FMA2(acc[1][0], p1, bl.x); FMA2(acc[1][1], p1, bl.y);
                FMA2(acc[1][2], p1, bh.x); FMA2(acc[1][3], p1, bh.y);
                FMA2(acc[2][0], p2, bl.x); FMA2(acc[2][1], p2, bl.y);
                FMA2(acc[2][2], p2, bh.x); FMA2(acc[2][3], p2, bh.y);
                FMA2(acc[3][0], p3, bl.x); FMA2(acc[3][1], p3, bl.y);
                FMA2(acc[3][2], p3, bh.x); FMA2(acc[3][3], p3, bh.y);
            }
        }
        __syncthreads();
    }

    // epilogue: write y + deterministic per-CTA partial sum/sumsq
    float* Ps = A;            // 32*64 floats
    float* Qs = A + 2048;     // 32*64 floats

    float s[8], q[8];
    #pragma unroll
    for (int j = 0; j < 8; j++) { s[j] = 0.0f; q[j] = 0.0f; }

    #pragma unroll
    for (int i = 0; i < 4; i++) {
        float y[8];
        unpack2(acc[i][0], y[0], y[1]);
        unpack2(acc[i][1], y[2], y[3]);
        unpack2(acc[i][2], y[4], y[5]);
        unpack2(acc[i][3], y[6], y[7]);
        const int m = tile0 + rg * 4 + i;
        *(float4*)(out + (size_t)m * CC + cg * 8)     = make_float4(y[0], y[1], y[2], y[3]);
        *(float4*)(out + (size_t)m * CC + cg * 8 + 4) = make_float4(y[4], y[5], y[6], y[7]);
        #pragma unroll
        for (int j = 0; j < 8; j++) { s[j] += y[j]; q[j] += y[j] * y[j]; }
    }
    #pragma unroll
    for (int j = 0; j < 8; j++) {
        Ps[rg * CC + cg * 8 + j] = s[j];
        Qs[rg * CC + cg * 8 + j] = q[j];
    }
    __syncthreads();
    if (tid < 128) {
        const float* src = (tid < 64) ? Ps : Qs;
        const int d = tid & 63;
        float a = 0.0f;
        #pragma unroll
        for (int r = 0; r < 32; r++) a += src[r * CC + d];
        partials[(size_t)blockIdx.x * 128 + tid] = a;
    }
}

// ---- BN stats reduce -> scale/shift (deterministic) -------------------------
__global__ void __launch_bounds__(512) reduce_kernel(
    const float* __restrict__ partials, int nct,
    const float* __restrict__ gamma, const float* __restrict__ beta, float invN)
{
    __shared__ float red[512];
    const int tid = threadIdx.x;
    const int c = tid & 63, which = (tid >> 6) & 1, part = tid >> 7;  // part 0..3
    float a = 0.0f;
    for (int cta = part; cta < nct; cta += 4)
        a += partials[(size_t)cta * 128 + which * 64 + c];
    red[tid] = a;
    __syncthreads();
    if (tid < 128) {
        red[tid] = red[tid] + red[tid + 128] + red[tid + 256] + red[tid + 384];
    }
    __syncthreads();
    if (tid < 64) {
        const float sum = red[tid];
        const float sq  = red[tid + 64];
        const float mean = sum * invN;
        const float var  = sq * invN - mean * mean;
        const float sc = gamma[tid] * rsqrtf(var + 1e-5f);
        g_scale[tid] = sc;
        g_shift[tid] = beta[tid] - mean * sc;
    }
}

// ---- elementwise: t = leaky(t*scale + shift) -------------------------------
__global__ void __launch_bounds__(256) bnleaky_kernel(float* __restrict__ t, int n4)
{
    const int i = blockIdx.x * blockDim.x + threadIdx.x;
    if (i >= n4) return;
    const int c = (i << 2) & 63;
    const float4 sc = *(const float4*)(g_scale + c);
    const float4 sh = *(const float4*)(g_shift + c);
    float4 v = ((const float4*)t)[i];
    float x;
    x = v.x * sc.x + sh.x; v.x = x > 0.0f ? x : LEAK * x;
    x = v.y * sc.y + sh.y; v.y = x > 0.0f ? x : LEAK * x;
    x = v.z * sc.z + sh.z; v.z = x > 0.0f ? x : LEAK * x;
    x = v.w * sc.w + sh.w; v.w = x > 0.0f ? x : LEAK * x;
    ((float4*)t)[i] = v;
}

// ---- elementwise: out = leaky(y*scale + shift + res) -----------------------
__global__ void __launch_bounds__(256) bnresleaky_kernel(
    const float* __restrict__ y, const float* __restrict__ res,
    float* __restrict__ outp, int n4)
{
    const int i = blockIdx.x * blockDim.x + threadIdx.x;
    if (i >= n4) return;
    const int c = (i << 2) & 63;
    const float4 sc = *(const float4*)(g_scale + c);
    const float4 sh = *(const float4*)(g_shift + c);
    float4 v = ((const float4*)y)[i];
    const float4 r = ((const float4*)res)[i];
    float x;
    x = v.x * sc.x + sh.x + r.x; v.x = x > 0.0f ? x : LEAK * x;
    x = v.y * sc.y + sh.y + r.y; v.y = x > 0.0f ? x : LEAK * x;
    x = v.z * sc.z + sh.z + r.z; v.z = x > 0.0f ? x : LEAK * x;
    x = v.w * sc.w + sh.w + r.w; v.w = x > 0.0f ? x : LEAK * x;
    ((float4*)outp)[i] = v;
}

// ============================================================================
extern "C" void kernel_launch(void* const* d_in, const int* in_sizes, int n_in,
                              void* d_out, int out_size)
{
    const float* features = (const float*)d_in[0];
    const int*   nidx     = (const int*)d_in[1];
    const void*  nmask    = d_in[2];
    const float* conv1w   = (const float*)d_in[3];
    const float* bn1g     = (const float*)d_in[4];
    const float* bn1b     = (const float*)d_in[5];
    const float* conv2w   = (const float*)d_in[6];
    const float* bn2g     = (const float*)d_in[7];
    const float* bn2b     = (const float*)d_in[8];
    float* out = (float*)d_out;

    const int N   = in_sizes[0] / CC;      // 131072
    const int nct = N / TM;                // 1024
    const int n4  = (N * CC) / 4;
    const float invN = 1.0f / (float)N;
    const int B = in_sizes[3] / (KK * CC * CC);  // 4 blocks

    float *pT, *pY, *pX, *pPart;
    cudaGetSymbolAddress((void**)&pT, g_T);
    cudaGetSymbolAddress((void**)&pY, g_Y);
    cudaGetSymbolAddress((void**)&pX, g_X);
    cudaGetSymbolAddress((void**)&pPart, g_part);

    cudaFuncSetAttribute(conv_kernel,
                         cudaFuncAttributeMaxDynamicSharedMemorySize, SMEM_BYTES);

    detect_kernel<<<1, 1>>>((const unsigned*)nmask);

    const float* xcur = features;
    for (int b = 0; b < B; b++) {
        const float* w1 = conv1w + (size_t)b * KK * CC * CC;
        const float* w2 = conv2w + (size_t)b * KK * CC * CC;

        conv_kernel<<<nct, 256, SMEM_BYTES>>>(xcur, w1, nidx, nmask, pT, pPart);
        reduce_kernel<<<1, 512>>>(pPart, nct, bn1g + b * CC, bn1b + b * CC, invN);
        bnleaky_kernel<<<(n4 + 255) / 256, 256>>>(pT, n4);

        conv_kernel<<<nct, 256, SMEM_BYTES>>>(pT, w2, nidx, nmask, pY, pPart);
        reduce_kernel<<<1, 512>>>(pPart, nct, bn2g + b * CC, bn2b + b * CC, invN);

        float* dst = (b == B - 1) ? out : pX;
        bnresleaky_kernel<<<(n4 + 255) / 256, 256>>>(pY, xcur, dst, n4);
        xcur = dst;
    }
}

// round 6
// speedup vs baseline: 1.4711x; 1.4711x over previous
#include <cuda_runtime.h>
#include <cuda_bf16.h>
#include <cstdint>
#include <cstddef>

#define CC 64
#define KK 9
#define TM 128
#define NMAX 131072
#define NTILES (NMAX/TM)
#define LEAK 0.33f

// SMEM: Wf fragments 147456 | A 4x16KB | idx 4608 | ss 4608
#define SM_WF  0
#define SM_A   147456
#define SM_IDX 212992
#define SM_SS  217600
#define SMEM_TOTAL 222208

// per-layer weight fragment image size in u32 (9 slices * 2 planes * 4 kc * 8 nt * 32 lanes * 2)
#define WF_LAYER 36864

__device__ float g_T[(size_t)NMAX*CC];
__device__ float g_Y[(size_t)NMAX*CC];
__device__ float g_X[(size_t)NMAX*CC];
__device__ __nv_bfloat16 g_Ahi[(size_t)NMAX*CC];
__device__ __nv_bfloat16 g_Alo[(size_t)NMAX*CC];
__device__ __nv_bfloat16 g_Bhi[(size_t)NMAX*CC];
__device__ __nv_bfloat16 g_Blo[(size_t)NMAX*CC];
__device__ unsigned g_Wf[(size_t)8*WF_LAYER];
__device__ float g_part[(size_t)NTILES*128];
__device__ float g_scale[CC];
__device__ float g_shift[CC];
__device__ int   g_mask_mode;

__device__ __forceinline__ void cpa16(unsigned d,const void* s,int ss){
    asm volatile("cp.async.cg.shared.global [%0], [%1], 16, %2;"::"r"(d),"l"(s),"r"(ss):"memory");
}
#define CP_COMMIT() asm volatile("cp.async.commit_group;":::"memory")
#define CP_WAIT(n)  asm volatile("cp.async.wait_group %0;"::"n"(n):"memory")
#define LDM4(a0,a1,a2,a3,ad) asm volatile( \
    "ldmatrix.sync.aligned.m8n8.x4.shared.b16 {%0,%1,%2,%3}, [%4];" \
    :"=r"(a0),"=r"(a1),"=r"(a2),"=r"(a3):"r"(ad))
#define LDS64(b0,b1,ad) asm volatile( \
    "ld.shared.v2.u32 {%0,%1}, [%2];":"=r"(b0),"=r"(b1):"r"(ad))
#define MMA(c,A0,A1,A2,A3,B0,B1) asm volatile( \
    "mma.sync.aligned.m16n8k16.row.col.f32.bf16.bf16.f32 " \
    "{%0,%1,%2,%3},{%4,%5,%6,%7},{%8,%9},{%0,%1,%2,%3};" \
    :"+f"((c)[0]),"+f"((c)[1]),"+f"((c)[2]),"+f"((c)[3]) \
    :"r"(A0),"r"(A1),"r"(A2),"r"(A3),"r"(B0),"r"(B1))

__device__ __forceinline__ unsigned short bf2u(__nv_bfloat16 b){
    union{__nv_bfloat16 h; unsigned short u;} c; c.h=b; return c.u;
}

__global__ void detect_kernel(const unsigned* __restrict__ m){
    if(threadIdx.x==0&&blockIdx.x==0){
        int f32ok=1; unsigned up=0;
        for(int i=0;i<256;i++){unsigned w=m[i]; if(w!=0u&&w!=0x3F800000u)f32ok=0; up|=(w&0xFFFFFF00u);}
        g_mask_mode = f32ok?2:(up?0:1);
    }
}

// Pack fp32 W[b][k][c][d] into mma B-fragment layout, hi/lo planes.
// b0 reg: W[c0..c0+1][d], b1: W[c0+8..c0+9][d]; c0=kc*16+(lane%4)*2, d=nt*8+lane/4
__global__ void wprep_kernel(const float* __restrict__ w1,const float* __restrict__ w2,int total){
    int i=blockIdx.x*blockDim.x+threadIdx.x; if(i>=total)return;
    const int lane=i&31, nt=(i>>5)&7, kc=(i>>8)&3, plane=(i>>10)&1;
    const int t=i>>11, slice=t%9, L=t/9;
    const int c0=kc*16+(lane&3)*2, d=nt*8+(lane>>2);
    const float* src=(L&1)?w2:w1;
    const float* S=src+((size_t)(L>>1)*9+slice)*4096;
    #pragma unroll
    for(int j=0;j<2;j++){
        const int c=c0+j*8;
        float f0=S[c*64+d], f1=S[(c+1)*64+d];
        __nv_bfloat16 h0=__float2bfloat16_rn(f0), h1=__float2bfloat16_rn(f1);
        unsigned short u0,u1;
        if(plane){
            u0=bf2u(__float2bfloat16_rn(f0-__bfloat162float(h0)));
            u1=bf2u(__float2bfloat16_rn(f1-__bfloat162float(h1)));
        } else { u0=bf2u(h0); u1=bf2u(h1); }
        g_Wf[(size_t)i*2+j]=((unsigned)u1<<16)|u0;
    }
}

__global__ void __launch_bounds__(256,1) conv_kernel(
    const __nv_bfloat16* __restrict__ xhi,const __nv_bfloat16* __restrict__ xlo,
    const unsigned* __restrict__ wf,const int* __restrict__ nidx,
    const void* __restrict__ nmask,float* __restrict__ out,
    float* __restrict__ partials,int ntiles)
{
    extern __shared__ __align__(16) char smem[];
    const unsigned sb=(unsigned)__cvta_generic_to_shared(smem);
    const int tid=threadIdx.x;
    int* idx_s=(int*)(smem+SM_IDX);
    int* ss_s =(int*)(smem+SM_SS);
    float* Ys =(float*)(smem+SM_A);

    // load this layer's W fragments once (147456 B)
    for(int i=tid;i<9216;i+=256)
        cpa16(sb+SM_WF+(unsigned)(i*16), (const char*)wf+(size_t)i*16, 16);
    CP_COMMIT(); CP_WAIT(0);
    __syncthreads();

    const int sr=tid>>1, sh=tid&1, rsw=sr&7;          // staging
    const int w=tid>>5, lane=tid&31;                  // compute
    const int rowbase=w<<4;
    const int rq=rowbase+(lane&15);
    const unsigned rbs=(unsigned)(rq*128);
    const int rx=rq&7, chsel=lane>>4;

    for(int t=blockIdx.x;t<ntiles;t+=gridDim.x){
        const int tile0=t*TM;
        {
            const int mode=g_mask_mode; const long gb=(long)tile0*KK;
            for(int i=tid;i<TM*KK;i+=256){
                idx_s[i]=nidx[gb+i];
                int mv;
                if(mode==0)      mv=((const unsigned char*)nmask)[gb+i];
                else if(mode==1) mv=((const int*)nmask)[gb+i]!=0;
                else             mv=((const float*)nmask)[gb+i]!=0.0f;
                ss_s[i]=mv?16:0;
            }
        }
        __syncthreads();
        {   // prologue: slice 0 -> buf0
            const int id=idx_s[sr*KK], ss=ss_s[sr*KK];
            const char* shi=(const char*)(xhi+(size_t)id*CC);
            const char* slo=(const char*)(xlo+(size_t)id*CC);
            const unsigned db=sb+SM_A+(unsigned)(sr*128);
            #pragma unroll
            for(int j=0;j<4;j++){
                const int ch=sh*4+j; const unsigned dc=(unsigned)((ch^rsw)<<4);
                cpa16(db+dc, shi+ch*16, ss);
                cpa16(db+16384+dc, slo+ch*16, ss);
            }
            CP_COMMIT();
        }

        float acc[32];
        #pragma unroll
        for(int i=0;i<32;i++) acc[i]=0.0f;

        for(int k=0;k<KK;k++){
            if(k<KK-1){
                const int nb=(k+1)&1;
                const int id=idx_s[sr*KK+k+1], ss=ss_s[sr*KK+k+1];
                const char* shi=(const char*)(xhi+(size_t)id*CC);
                const char* slo=(const char*)(xlo+(size_t)id*CC);
                const unsigned db=sb+SM_A+(unsigned)(nb*32768+sr*128);
                #pragma unroll
                for(int j=0;j<4;j++){
                    const int ch=sh*4+j; const unsigned dc=(unsigned)((ch^rsw)<<4);
                    cpa16(db+dc, shi+ch*16, ss);
                    cpa16(db+16384+dc, slo+ch*16, ss);
                }
                CP_COMMIT(); CP_WAIT(1);
            } else { CP_WAIT(0); }
            __syncthreads();

            const unsigned Ab=sb+SM_A+(unsigned)((k&1)*32768);
            #pragma unroll
            for(int kc=0;kc<4;kc++){
                const unsigned ch=(unsigned)((kc<<1)+chsel);
                const unsigned ah=Ab+rbs+((ch^(unsigned)rx)<<4);
                unsigned a0,a1,a2,a3,l0,l1,l2,l3;
                LDM4(a0,a1,a2,a3,ah);
                LDM4(l0,l1,l2,l3,ah+16384u);
                const unsigned wbh=sb+SM_WF+(unsigned)((k*8+kc)*2048+lane*8);
                const unsigned wbl=wbh+8192u;
                #pragma unroll
                for(int nt=0;nt<8;nt++){
                    unsigned b0,b1,c0,c1;
                    LDS64(b0,b1,wbh+(unsigned)(nt*256));
                    MMA(acc+nt*4,a0,a1,a2,a3,b0,b1);
                    MMA(acc+nt*4,l0,l1,l2,l3,b0,b1);
                    LDS64(c0,c1,wbl+(unsigned)(nt*256));
                    MMA(acc+nt*4,a0,a1,a2,a3,c0,c1);
                }
            }
            __syncthreads();
        }

        // epilogue: accums -> swizzled Ys (reuses buf0 region)
        {
            const int row0=rowbase+(lane>>2), row1=row0+8;
            #pragma unroll
            for(int nt=0;nt<8;nt++){
                const int c=nt*8+(lane&3)*2;
                const int c4=c>>2, ci=c&3;
                *(float2*)(Ys+row0*64+(((c4^(row0&7))<<2)|ci))=make_float2(acc[nt*4],acc[nt*4+1]);
                *(float2*)(Ys+row1*64+(((c4^(row1&7))<<2)|ci))=make_float2(acc[nt*4+2],acc[nt*4+3]);
            }
        }
        __syncthreads();
        if(tid<128){
            const int c=tid&63; const bool sq=tid>=64;
            const int c4=c>>2, ci=c&3;
            float a=0.0f;
            for(int r=0;r<128;r++){
                float v=Ys[r*64+(((c4^(r&7))<<2)|ci)];
                a += sq ? v*v : v;
            }
            partials[(size_t)t*128+tid]=a;
        } else {
            const int lt=tid-128;
            float* og=out+(size_t)tile0*CC;
            for(int i=lt;i<2048;i+=128){
                const int r=i>>4, c4=i&15;
                *(float4*)(og+i*4)=*(float4*)(Ys+r*64+((c4^(r&7))<<2));
            }
        }
        __syncthreads();
    }
}

__global__ void __launch_bounds__(512) reduce_kernel(
    const float* __restrict__ partials,int nct,
    const float* __restrict__ gamma,const float* __restrict__ beta,float invN)
{
    __shared__ float red[512];
    const int tid=threadIdx.x;
    const int c=tid&63, which=(tid>>6)&1, part=tid>>7;
    float a=0.0f;
    for(int cta=part;cta<nct;cta+=4) a+=partials[(size_t)cta*128+which*64+c];
    red[tid]=a; __syncthreads();
    if(tid<128) red[tid]=red[tid]+red[tid+128]+red[tid+256]+red[tid+384];
    __syncthreads();
    if(tid<64){
        float mean=red[tid]*invN;
        float var=red[tid+64]*invN-mean*mean;
        float sc=gamma[tid]*rsqrtf(var+1e-5f);
        g_scale[tid]=sc; g_shift[tid]=beta[tid]-mean*sc;
    }
}

__device__ __forceinline__ void split_store(__nv_bfloat16* hp,__nv_bfloat16* lp,size_t i4,float4 z){
    union{__nv_bfloat16 b[4];uint2 u;}H,L;
    float zz[4]={z.x,z.y,z.z,z.w};
    #pragma unroll
    for(int j=0;j<4;j++){
        H.b[j]=__float2bfloat16_rn(zz[j]);
        L.b[j]=__float2bfloat16_rn(zz[j]-__bfloat162float(H.b[j]));
    }
    *(uint2*)(hp+i4*4)=H.u; *(uint2*)(lp+i4*4)=L.u;
}

__global__ void __launch_bounds__(256) convert_kernel(
    const float* __restrict__ x,__nv_bfloat16* hi,__nv_bfloat16* lo,int n4){
    int i=blockIdx.x*blockDim.x+threadIdx.x; if(i>=n4)return;
    split_store(hi,lo,(size_t)i,((const float4*)x)[i]);
}

__global__ void __launch_bounds__(256) bnleaky_kernel(
    const float* __restrict__ t,__nv_bfloat16* hi,__nv_bfloat16* lo,int n4){
    int i=blockIdx.x*blockDim.x+threadIdx.x; if(i>=n4)return;
    const int c=(i<<2)&63;
    const float4 sc=*(const float4*)(g_scale+c), sh=*(const float4*)(g_shift+c);
    float4 v=((const float4*)t)[i]; float x;
    x=v.x*sc.x+sh.x; v.x=x>0?x:LEAK*x;
    x=v.y*sc.y+sh.y; v.y=x>0?x:LEAK*x;
    x=v.z*sc.z+sh.z; v.z=x>0?x:LEAK*x;
    x=v.w*sc.w+sh.w; v.w=x>0?x:LEAK*x;
    split_store(hi,lo,(size_t)i,v);
}

__global__ void __launch_bounds__(256) bnresleaky_kernel(
    const float* __restrict__ y,const float* __restrict__ res,float* __restrict__ op,
    __nv_bfloat16* hi,__nv_bfloat16* lo,int wp,int n4){
    int i=blockIdx.x*blockDim.x+threadIdx.x; if(i>=n4)return;
    const int c=(i<<2)&63;
    const float4 sc=*(const float4*)(g_scale+c), sh=*(const float4*)(g_shift+c);
    float4 v=((const float4*)y)[i]; const float4 r=((const float4*)res)[i]; float x;
    x=v.x*sc.x+sh.x+r.x; v.x=x>0?x:LEAK*x;
    x=v.y*sc.y+sh.y+r.y; v.y=x>0?x:LEAK*x;
    x=v.z*sc.z+sh.z+r.z; v.z=x>0?x:LEAK*x;
    x=v.w*sc.w+sh.w+r.w; v.w=x>0?x:LEAK*x;
    ((float4*)op)[i]=v;
    if(wp) split_store(hi,lo,(size_t)i,v);
}

extern "C" void kernel_launch(void* const* d_in,const int* in_sizes,int n_in,
                              void* d_out,int out_size)
{
    const float* features=(const float*)d_in[0];
    const int*   nidx    =(const int*)d_in[1];
    const void*  nmask   =d_in[2];
    const float* conv1w  =(const float*)d_in[3];
    const float* bn1g    =(const float*)d_in[4];
    const float* bn1b    =(const float*)d_in[5];
    const float* conv2w  =(const float*)d_in[6];
    const float* bn2g    =(const float*)d_in[7];
    const float* bn2b    =(const float*)d_in[8];
    float* out=(float*)d_out;

    const int N=in_sizes[0]/CC, nct=N/TM, n4=(N*CC)/4;
    const float invN=1.0f/(float)N;
    const int B=in_sizes[3]/(KK*CC*CC);

    float *pT,*pY,*pX,*pPart; __nv_bfloat16 *pAh,*pAl,*pBh,*pBl; unsigned* pW;
    cudaGetSymbolAddress((void**)&pT,g_T);
    cudaGetSymbolAddress((void**)&pY,g_Y);
    cudaGetSymbolAddress((void**)&pX,g_X);
    cudaGetSymbolAddress((void**)&pPart,g_part);
    cudaGetSymbolAddress((void**)&pAh,g_Ahi);
    cudaGetSymbolAddress((void**)&pAl,g_Alo);
    cudaGetSymbolAddress((void**)&pBh,g_Bhi);
    cudaGetSymbolAddress((void**)&pBl,g_Blo);
    cudaGetSymbolAddress((void**)&pW,g_Wf);

    cudaFuncSetAttribute(conv_kernel,cudaFuncAttributeMaxDynamicSharedMemorySize,SMEM_TOTAL);

    detect_kernel<<<1,1>>>((const unsigned*)nmask);
    wprep_kernel<<<(B*2*18432+255)/256,256>>>(conv1w,conv2w,B*2*18432);
    convert_kernel<<<(n4+255)/256,256>>>(features,pAh,pAl,n4);

    const float* xcur=features;
    for(int b=0;b<B;b++){
        // FIX (R5): per-layer Wf stride is WF_LAYER u32 (was 2x too large)
        conv_kernel<<<148,256,SMEM_TOTAL>>>(pAh,pAl,pW+(size_t)(b*2)*WF_LAYER,nidx,nmask,pT,pPart,nct);
        reduce_kernel<<<1,512>>>(pPart,nct,bn1g+b*CC,bn1b+b*CC,invN);
        bnleaky_kernel<<<(n4+255)/256,256>>>(pT,pBh,pBl,n4);

        conv_kernel<<<148,256,SMEM_TOTAL>>>(pBh,pBl,pW+(size_t)(b*2+1)*WF_LAYER,nidx,nmask,pY,pPart,nct);
        reduce_kernel<<<1,512>>>(pPart,nct,bn2g+b*CC,bn2b+b*CC,invN);

        float* dst=(b==B-1)?out:pX;
        bnresleaky_kernel<<<(n4+255)/256,256>>>(pY,xcur,dst,pAh,pAl,b<B-1,n4);
        xcur=dst;
    }
}

// round 7
// speedup vs baseline: 2.3130x; 1.5722x over previous
#include <cuda_runtime.h>
#include <cuda_bf16.h>
#include <cstdint>
#include <cstddef>

#define CC 64
#define KK 9
#define TM 128
#define NMAX 131072
#define NTILES (NMAX/TM)
#define LEAK 0.33f

// SMEM: Wf fragments 147456 | A 4x16KB | idx 4608 | ss 4608
#define SM_WF  0
#define SM_A   147456
#define SM_IDX 212992
#define SM_SS  217600
#define SMEM_TOTAL 222208

// per-layer weight fragment image size in u32
#define WF_LAYER 36864

__device__ float g_T[(size_t)NMAX*CC];
__device__ float g_Y[(size_t)NMAX*CC];
__device__ float g_X[(size_t)NMAX*CC];
__device__ __nv_bfloat16 g_Ahi[(size_t)NMAX*CC];
__device__ __nv_bfloat16 g_Alo[(size_t)NMAX*CC];
__device__ __nv_bfloat16 g_Bhi[(size_t)NMAX*CC];
__device__ __nv_bfloat16 g_Blo[(size_t)NMAX*CC];
__device__ unsigned g_Wf[(size_t)8*WF_LAYER];
__device__ float g_part[(size_t)NTILES*128];
__device__ float g_scale[CC];
__device__ float g_shift[CC];
__device__ int   g_mask_mode;

__device__ __forceinline__ void cpa16(unsigned d,const void* s,int ss){
    asm volatile("cp.async.cg.shared.global [%0], [%1], 16, %2;"::"r"(d),"l"(s),"r"(ss):"memory");
}
#define CP_COMMIT() asm volatile("cp.async.commit_group;":::"memory")
#define CP_WAIT(n)  asm volatile("cp.async.wait_group %0;"::"n"(n):"memory")
#define LDM4(a0,a1,a2,a3,ad) asm volatile( \
    "ldmatrix.sync.aligned.m8n8.x4.shared.b16 {%0,%1,%2,%3}, [%4];" \
    :"=r"(a0),"=r"(a1),"=r"(a2),"=r"(a3):"r"(ad))
#define LDS64(b0,b1,ad) asm volatile( \
    "ld.shared.v2.u32 {%0,%1}, [%2];":"=r"(b0),"=r"(b1):"r"(ad))
#define MMA(c,A0,A1,A2,A3,B0,B1) asm volatile( \
    "mma.sync.aligned.m16n8k16.row.col.f32.bf16.bf16.f32 " \
    "{%0,%1,%2,%3},{%4,%5,%6,%7},{%8,%9},{%0,%1,%2,%3};" \
    :"+f"((c)[0]),"+f"((c)[1]),"+f"((c)[2]),"+f"((c)[3]) \
    :"r"(A0),"r"(A1),"r"(A2),"r"(A3),"r"(B0),"r"(B1))

__device__ __forceinline__ unsigned short bf2u(__nv_bfloat16 b){
    union{__nv_bfloat16 h; unsigned short u;} c; c.h=b; return c.u;
}

__global__ void detect_kernel(const unsigned* __restrict__ m){
    if(threadIdx.x==0&&blockIdx.x==0){
        int f32ok=1; unsigned up=0;
        for(int i=0;i<256;i++){unsigned w=m[i]; if(w!=0u&&w!=0x3F800000u)f32ok=0; up|=(w&0xFFFFFF00u);}
        g_mask_mode = f32ok?2:(up?0:1);
    }
}

// Pack fp32 W[b][k][c][d] into mma B-fragment layout, hi/lo planes.
__global__ void wprep_kernel(const float* __restrict__ w1,const float* __restrict__ w2,int total){
    int i=blockIdx.x*blockDim.x+threadIdx.x; if(i>=total)return;
    const int lane=i&31, nt=(i>>5)&7, kc=(i>>8)&3, plane=(i>>10)&1;
    const int t=i>>11, slice=t%9, L=t/9;
    const int c0=kc*16+(lane&3)*2, d=nt*8+(lane>>2);
    const float* src=(L&1)?w2:w1;
    const float* S=src+((size_t)(L>>1)*9+slice)*4096;
    #pragma unroll
    for(int j=0;j<2;j++){
        const int c=c0+j*8;
        float f0=S[c*64+d], f1=S[(c+1)*64+d];
        __nv_bfloat16 h0=__float2bfloat16_rn(f0), h1=__float2bfloat16_rn(f1);
        unsigned short u0,u1;
        if(plane){
            u0=bf2u(__float2bfloat16_rn(f0-__bfloat162float(h0)));
            u1=bf2u(__float2bfloat16_rn(f1-__bfloat162float(h1)));
        } else { u0=bf2u(h0); u1=bf2u(h1); }
        g_Wf[(size_t)i*2+j]=((unsigned)u1<<16)|u0;
    }
}

__global__ void __launch_bounds__(512,1) conv_kernel(
    const __nv_bfloat16* __restrict__ xhi,const __nv_bfloat16* __restrict__ xlo,
    const unsigned* __restrict__ wf,const int* __restrict__ nidx,
    const void* __restrict__ nmask,float* __restrict__ out,
    float* __restrict__ partials,int ntiles)
{
    extern __shared__ __align__(16) char smem[];
    const unsigned sb=(unsigned)__cvta_generic_to_shared(smem);
    const int tid=threadIdx.x;
    int* idx_s=(int*)(smem+SM_IDX);
    int* ss_s =(int*)(smem+SM_SS);
    float* Ys =(float*)(smem+SM_A);          // epilogue scratch = buf0 region (32KB)
    float* Sc =(float*)(smem+SM_SS);         // epilogue partial scratch (reloaded per tile)

    // load this layer's W fragments once (147456 B)
    for(int i=tid;i<9216;i+=512)
        cpa16(sb+SM_WF+(unsigned)(i*16), (const char*)wf+(size_t)i*16, 16);
    CP_COMMIT(); CP_WAIT(0);
    __syncthreads();

    // staging: 4 threads per row, 2 hi + 2 lo 16B chunks each
    const int sr=tid>>2, q=tid&3, rsw=sr&7;
    // compute: warp w -> rows (w&7)*16..+16, nt quad (w>>3)*4..+4
    const int w=tid>>5, lane=tid&31;
    const int rw=w&7, nth=(w>>3)<<2;
    const int rowbase=rw<<4;
    const int rq=rowbase+(lane&15);
    const unsigned rbs=(unsigned)(rq*128);
    const int rx=rq&7, chsel=lane>>4;

    for(int t=blockIdx.x;t<ntiles;t+=gridDim.x){
        const int tile0=t*TM;
        {
            const int mode=g_mask_mode; const long gb=(long)tile0*KK;
            for(int i=tid;i<TM*KK;i+=512){
                idx_s[i]=nidx[gb+i];
                int mv;
                if(mode==0)      mv=((const unsigned char*)nmask)[gb+i];
                else if(mode==1) mv=((const int*)nmask)[gb+i]!=0;
                else             mv=((const float*)nmask)[gb+i]!=0.0f;
                ss_s[i]=mv?16:0;
            }
        }
        __syncthreads();
        {   // prologue: slice 0 -> buf0
            const int id=idx_s[sr*KK], ss=ss_s[sr*KK];
            const char* shi=(const char*)(xhi+(size_t)id*CC);
            const char* slo=(const char*)(xlo+(size_t)id*CC);
            const unsigned db=sb+SM_A+(unsigned)(sr*128);
            #pragma unroll
            for(int j=0;j<2;j++){
                const int ch=q*2+j; const unsigned dc=(unsigned)((ch^rsw)<<4);
                cpa16(db+dc, shi+ch*16, ss);
                cpa16(db+16384+dc, slo+ch*16, ss);
            }
            CP_COMMIT();
        }

        float acc[16];
        #pragma unroll
        for(int i=0;i<16;i++) acc[i]=0.0f;

        for(int k=0;k<KK;k++){
            if(k<KK-1){
                const int nb=(k+1)&1;
                const int id=idx_s[sr*KK+k+1], ss=ss_s[sr*KK+k+1];
                const char* shi=(const char*)(xhi+(size_t)id*CC);
                const char* slo=(const char*)(xlo+(size_t)id*CC);
                const unsigned db=sb+SM_A+(unsigned)(nb*32768+sr*128);
                #pragma unroll
                for(int j=0;j<2;j++){
                    const int ch=q*2+j; const unsigned dc=(unsigned)((ch^rsw)<<4);
                    cpa16(db+dc, shi+ch*16, ss);
                    cpa16(db+16384+dc, slo+ch*16, ss);
                }
                CP_COMMIT(); CP_WAIT(1);
            } else { CP_WAIT(0); }
            __syncthreads();

            const unsigned Ab=sb+SM_A+(unsigned)((k&1)*32768);
            #pragma unroll
            for(int kc=0;kc<4;kc++){
                const unsigned ch=(unsigned)((kc<<1)+chsel);
                const unsigned ah=Ab+rbs+((ch^(unsigned)rx)<<4);
                unsigned a0,a1,a2,a3,l0,l1,l2,l3;
                LDM4(a0,a1,a2,a3,ah);
                LDM4(l0,l1,l2,l3,ah+16384u);
                const unsigned wbh=sb+SM_WF+(unsigned)((k*8+kc)*2048+lane*8);
                const unsigned wbl=wbh+8192u;
                #pragma unroll
                for(int j=0;j<4;j++){
                    const int nt=nth+j;
                    unsigned b0,b1,c0,c1;
                    LDS64(b0,b1,wbh+(unsigned)(nt*256));
                    MMA(acc+j*4,a0,a1,a2,a3,b0,b1);
                    MMA(acc+j*4,l0,l1,l2,l3,b0,b1);
                    LDS64(c0,c1,wbl+(unsigned)(nt*256));
                    MMA(acc+j*4,a0,a1,a2,a3,c0,c1);
                }
            }
            __syncthreads();
        }

        // accums -> swizzled Ys
        {
            const int row0=rowbase+(lane>>2), row1=row0+8;
            #pragma unroll
            for(int j=0;j<4;j++){
                const int c=(nth+j)*8+(lane&3)*2;
                const int c4=c>>2, ci=c&3;
                *(float2*)(Ys+row0*64+(((c4^(row0&7))<<2)|ci))=make_float2(acc[j*4],acc[j*4+1]);
                *(float2*)(Ys+row1*64+(((c4^(row1&7))<<2)|ci))=make_float2(acc[j*4+2],acc[j*4+3]);
            }
        }
        __syncthreads();
        if(tid<256){
            // partials: c (64) x {sum,sumsq} (2) x half (2); 64 rows each
            const int c=tid&63; const bool sq=(tid>>6)&1; const int h=tid>>7;
            const int c4=c>>2, ci=c&3;
            float a=0.0f;
            for(int r=h*64;r<h*64+64;r++){
                float v=Ys[r*64+(((c4^(r&7))<<2)|ci)];
                a += sq ? v*v : v;
            }
            Sc[tid]=a;
        } else {
            const int lt=tid-256;
            float* og=out+(size_t)tile0*CC;
            for(int i=lt;i<2048;i+=256){
                const int r=i>>4, c4=i&15;
                *(float4*)(og+i*4)=*(float4*)(Ys+r*64+((c4^(r&7))<<2));
            }
        }
        __syncthreads();
        if(tid<128) partials[(size_t)t*128+tid]=Sc[tid]+Sc[tid+128];
        __syncthreads();
    }
}

__global__ void __launch_bounds__(1024) reduce_kernel(
    const float* __restrict__ partials,int nct,
    const float* __restrict__ gamma,const float* __restrict__ beta,float invN)
{
    __shared__ float red[1024];
    const int tid=threadIdx.x;
    const int c=tid&63, which=(tid>>6)&1, part=tid>>7;   // part 0..7
    float a=0.0f;
    for(int cta=part;cta<nct;cta+=8) a+=partials[(size_t)cta*128+which*64+c];
    red[tid]=a; __syncthreads();
    if(tid<512) red[tid]+=red[tid+512];
    __syncthreads();
    if(tid<256) red[tid]+=red[tid+256];
    __syncthreads();
    if(tid<128) red[tid]+=red[tid+128];
    __syncthreads();
    if(tid<64){
        float mean=red[tid]*invN;
        float var=red[tid+64]*invN-mean*mean;
        float sc=gamma[tid]*rsqrtf(var+1e-5f);
        g_scale[tid]=sc; g_shift[tid]=beta[tid]-mean*sc;
    }
}

__device__ __forceinline__ void split_store(__nv_bfloat16* hp,__nv_bfloat16* lp,size_t i4,float4 z){
    union{__nv_bfloat16 b[4];uint2 u;}H,L;
    float zz[4]={z.x,z.y,z.z,z.w};
    #pragma unroll
    for(int j=0;j<4;j++){
        H.b[j]=__float2bfloat16_rn(zz[j]);
        L.b[j]=__float2bfloat16_rn(zz[j]-__bfloat162float(H.b[j]));
    }
    *(uint2*)(hp+i4*4)=H.u; *(uint2*)(lp+i4*4)=L.u;
}

__global__ void __launch_bounds__(256) convert_kernel(
    const float* __restrict__ x,__nv_bfloat16* hi,__nv_bfloat16* lo,int n4){
    int i=blockIdx.x*blockDim.x+threadIdx.x; if(i>=n4)return;
    split_store(hi,lo,(size_t)i,((const float4*)x)[i]);
}

__global__ void __launch_bounds__(256) bnleaky_kernel(
    const float* __restrict__ t,__nv_bfloat16* hi,__nv_bfloat16* lo,int n4){
    int i=blockIdx.x*blockDim.x+threadIdx.x; if(i>=n4)return;
    const int c=(i<<2)&63;
    const float4 sc=*(const float4*)(g_scale+c), sh=*(const float4*)(g_shift+c);
    float4 v=((const float4*)t)[i]; float x;
    x=v.x*sc.x+sh.x; v.x=x>0?x:LEAK*x;
    x=v.y*sc.y+sh.y; v.y=x>0?x:LEAK*x;
    x=v.z*sc.z+sh.z; v.z=x>0?x:LEAK*x;
    x=v.w*sc.w+sh.w; v.w=x>0?x:LEAK*x;
    split_store(hi,lo,(size_t)i,v);
}

__global__ void __launch_bounds__(256) bnresleaky_kernel(
    const float* __restrict__ y,const float* __restrict__ res,float* __restrict__ op,
    __nv_bfloat16* hi,__nv_bfloat16* lo,int wp,int n4){
    int i=blockIdx.x*blockDim.x+threadIdx.x; if(i>=n4)return;
    const int c=(i<<2)&63;
    const float4 sc=*(const float4*)(g_scale+c), sh=*(const float4*)(g_shift+c);
    float4 v=((const float4*)y)[i]; const float4 r=((const float4*)res)[i]; float x;
    x=v.x*sc.x+sh.x+r.x; v.x=x>0?x:LEAK*x;
    x=v.y*sc.y+sh.y+r.y; v.y=x>0?x:LEAK*x;
    x=v.z*sc.z+sh.z+r.z; v.z=x>0?x:LEAK*x;
    x=v.w*sc.w+sh.w+r.w; v.w=x>0?x:LEAK*x;
    ((float4*)op)[i]=v;
    if(wp) split_store(hi,lo,(size_t)i,v);
}

extern "C" void kernel_launch(void* const* d_in,const int* in_sizes,int n_in,
                              void* d_out,int out_size)
{
    const float* features=(const float*)d_in[0];
    const int*   nidx    =(const int*)d_in[1];
    const void*  nmask   =d_in[2];
    const float* conv1w  =(const float*)d_in[3];
    const float* bn1g    =(const float*)d_in[4];
    const float* bn1b    =(const float*)d_in[5];
    const float* conv2w  =(const float*)d_in[6];
    const float* bn2g    =(const float*)d_in[7];
    const float* bn2b    =(const float*)d_in[8];
    float* out=(float*)d_out;

    const int N=in_sizes[0]/CC, nct=N/TM, n4=(N*CC)/4;
    const float invN=1.0f/(float)N;
    const int B=in_sizes[3]/(KK*CC*CC);

    float *pT,*pY,*pX,*pPart; __nv_bfloat16 *pAh,*pAl,*pBh,*pBl; unsigned* pW;
    cudaGetSymbolAddress((void**)&pT,g_T);
    cudaGetSymbolAddress((void**)&pY,g_Y);
    cudaGetSymbolAddress((void**)&pX,g_X);
    cudaGetSymbolAddress((void**)&pPart,g_part);
    cudaGetSymbolAddress((void**)&pAh,g_Ahi);
    cudaGetSymbolAddress((void**)&pAl,g_Alo);
    cudaGetSymbolAddress((void**)&pBh,g_Bhi);
    cudaGetSymbolAddress((void**)&pBl,g_Blo);
    cudaGetSymbolAddress((void**)&pW,g_Wf);

    cudaFuncSetAttribute(conv_kernel,cudaFuncAttributeMaxDynamicSharedMemorySize,SMEM_TOTAL);

    detect_kernel<<<1,1>>>((const unsigned*)nmask);
    wprep_kernel<<<(B*2*18432+255)/256,256>>>(conv1w,conv2w,B*2*18432);
    convert_kernel<<<(n4+255)/256,256>>>(features,pAh,pAl,n4);

    const float* xcur=features;
    for(int b=0;b<B;b++){
        conv_kernel<<<148,512,SMEM_TOTAL>>>(pAh,pAl,pW+(size_t)(b*2)*WF_LAYER,nidx,nmask,pT,pPart,nct);
        reduce_kernel<<<1,1024>>>(pPart,nct,bn1g+b*CC,bn1b+b*CC,invN);
        bnleaky_kernel<<<(n4+255)/256,256>>>(pT,pBh,pBl,n4);

        conv_kernel<<<148,512,SMEM_TOTAL>>>(pBh,pBl,pW+(size_t)(b*2+1)*WF_LAYER,nidx,nmask,pY,pPart,nct);
        reduce_kernel<<<1,1024>>>(pPart,nct,bn2g+b*CC,bn2b+b*CC,invN);

        float* dst=(b==B-1)?out:pX;
        bnresleaky_kernel<<<(n4+255)/256,256>>>(pY,xcur,dst,pAh,pAl,b<B-1,n4);
        xcur=dst;
    }
}